// round 1
// baseline (speedup 1.0000x reference)
#include <cuda_runtime.h>
#include <cuda_bf16.h>
#include <cstddef>

#define NN   50000
#define NE   800000
#define DIN  256
#define DHID 256
#define DOUT 128

// ---------------- scratch (device globals; no allocation allowed) ----------------
__device__ float g_outnorm[NN];
__device__ float g_innorm[NN];
__device__ float g_t[(size_t)NN * DHID];    // pre-aggregation transformed features
__device__ float g_agg[(size_t)NN * DHID];  // aggregation accumulator

// ---------------- degree / norm kernels ----------------
__global__ void k_zero_norms() {
    int i = blockIdx.x * blockDim.x + threadIdx.x;
    if (i < NN) { g_outnorm[i] = 0.f; g_innorm[i] = 0.f; }
}

__global__ void k_degree(const int* __restrict__ src, const int* __restrict__ dst) {
    int e = blockIdx.x * blockDim.x + threadIdx.x;
    if (e < NE) {
        atomicAdd(&g_outnorm[src[e]], 1.f);
        atomicAdd(&g_innorm[dst[e]], 1.f);
    }
}

__global__ void k_fin_norms() {
    int i = blockIdx.x * blockDim.x + threadIdx.x;
    if (i < NN) {
        g_outnorm[i] = rsqrtf(fmaxf(g_outnorm[i], 1.f));
        g_innorm[i]  = rsqrtf(fmaxf(g_innorm[i], 1.f));
    }
}

__global__ void k_zero_agg() {
    int i = blockIdx.x * blockDim.x + threadIdx.x;
    if (i < NN * (DHID / 4))
        ((float4*)g_agg)[i] = make_float4(0.f, 0.f, 0.f, 0.f);
}

// ---------------- edge scatter (SpMM): agg[dst] += t[src] ----------------
__device__ __forceinline__ void red_add_v4(float* addr, float4 v) {
    asm volatile("red.global.add.v4.f32 [%0], {%1, %2, %3, %4};"
                 :: "l"(addr), "f"(v.x), "f"(v.y), "f"(v.z), "f"(v.w)
                 : "memory");
}

__global__ void k_scatter(const float* __restrict__ t,
                          const int* __restrict__ src, const int* __restrict__ dst) {
    int w    = (blockIdx.x * blockDim.x + threadIdx.x) >> 5;
    int lane = threadIdx.x & 31;
    if (w >= NE) return;
    int s = src[w];
    int d = dst[w];
    const float4* ts = (const float4*)(t + (size_t)s * DHID);
    float*        ad = g_agg + (size_t)d * DHID;
    float4 v0 = ts[lane];
    float4 v1 = ts[lane + 32];
    red_add_v4(ad + lane * 4, v0);
    red_add_v4(ad + (lane + 32) * 4, v1);
}

// ---------------- GEMM: C[M,Ncols] = (A * rowscale) @ B ----------------
// TRANSB=0: B element (k,n) = B[k*ld + n]; SPLITB: cols [0,128)->B0, [128,256)->B1 (ld=DOUT)
// TRANSB=1: B element (k,n) = B0[n*K + k]
template<int TRANSB, int SPLITB>
__global__ void __launch_bounds__(256, 2)
k_gemm(const float* __restrict__ A, const float* __restrict__ rowscale,
       const float* __restrict__ B0, const float* __restrict__ B1,
       float* __restrict__ C, int M, int Ncols, int K)
{
    constexpr int BM = 128, BN = 128, BK = 8;
    __shared__ float As[BK][BM + 4];
    __shared__ float Bs[BK][BN + 4];

    const int tid  = threadIdx.x;
    const int row0 = blockIdx.y * BM;
    const int col0 = blockIdx.x * BN;
    const int tx   = tid & 15;
    const int ty   = tid >> 4;

    float acc[8][8];
#pragma unroll
    for (int i = 0; i < 8; i++)
#pragma unroll
        for (int j = 0; j < 8; j++) acc[i][j] = 0.f;

    // A tile load mapping: one float4 per thread
    const int am = tid >> 1;
    const int ak = (tid & 1) * 4;
    const bool avalid = (row0 + am) < M;
    const float* Ap = A + (size_t)(row0 + am) * K + ak;
    float ascale = 1.f;
    if (avalid && rowscale) ascale = rowscale[row0 + am];

    // B tile load mapping
    const float* Bp;
    int bstep, bn, bk;
    if constexpr (TRANSB) {
        bn = tid >> 1;
        bk = (tid & 1) * 4;
        Bp = B0 + (size_t)(col0 + bn) * K + bk;
        bstep = BK;
    } else {
        bk = tid >> 5;
        bn = (tid & 31) * 4;
        if constexpr (SPLITB) {
            const float* Bsel = (col0 == 0) ? B0 : B1;
            Bp = Bsel + (size_t)bk * DOUT + bn;
            bstep = BK * DOUT;
        } else {
            Bp = B0 + (size_t)bk * Ncols + col0 + bn;
            bstep = BK * Ncols;
        }
    }

    for (int k0 = 0; k0 < K; k0 += BK) {
        float4 av = make_float4(0.f, 0.f, 0.f, 0.f);
        if (avalid) av = *(const float4*)Ap;
        As[ak + 0][am] = av.x * ascale;
        As[ak + 1][am] = av.y * ascale;
        As[ak + 2][am] = av.z * ascale;
        As[ak + 3][am] = av.w * ascale;
        if constexpr (TRANSB) {
            float4 bv = *(const float4*)Bp;
            Bs[bk + 0][bn] = bv.x;
            Bs[bk + 1][bn] = bv.y;
            Bs[bk + 2][bn] = bv.z;
            Bs[bk + 3][bn] = bv.w;
        } else {
            *(float4*)&Bs[bk][bn] = *(const float4*)Bp;
        }
        __syncthreads();

#pragma unroll
        for (int kk = 0; kk < BK; kk++) {
            float4 a0  = *(const float4*)&As[kk][ty * 8];
            float4 a1  = *(const float4*)&As[kk][ty * 8 + 4];
            float4 bv0 = *(const float4*)&Bs[kk][tx * 8];
            float4 bv1 = *(const float4*)&Bs[kk][tx * 8 + 4];
            float a[8] = {a0.x, a0.y, a0.z, a0.w, a1.x, a1.y, a1.z, a1.w};
            float b[8] = {bv0.x, bv0.y, bv0.z, bv0.w, bv1.x, bv1.y, bv1.z, bv1.w};
#pragma unroll
            for (int i = 0; i < 8; i++)
#pragma unroll
                for (int j = 0; j < 8; j++)
                    acc[i][j] += a[i] * b[j];
        }
        __syncthreads();
        Ap += BK;
        Bp += bstep;
    }

#pragma unroll
    for (int i = 0; i < 8; i++) {
        int row = row0 + ty * 8 + i;
        if (row < M) {
            float* cp = C + (size_t)row * Ncols + col0 + tx * 8;
            *(float4*)cp       = make_float4(acc[i][0], acc[i][1], acc[i][2], acc[i][3]);
            *(float4*)(cp + 4) = make_float4(acc[i][4], acc[i][5], acc[i][6], acc[i][7]);
        }
    }
}

// ---------------- epilogues ----------------
// h = relu(agg * in_norm + b1)
__global__ void k_epilogue_h(const float* __restrict__ b1, float* __restrict__ h) {
    int idx = blockIdx.x * blockDim.x + threadIdx.x;   // float4 index over NN*256/4
    if (idx >= NN * (DHID / 4)) return;
    int n  = idx >> 6;
    int c4 = idx & 63;
    float s  = g_innorm[n];
    float4 v = ((const float4*)g_agg)[idx];
    float4 b = ((const float4*)b1)[c4];
    float4 r;
    r.x = fmaxf(fmaf(v.x, s, b.x), 0.f);
    r.y = fmaxf(fmaf(v.y, s, b.y), 0.f);
    r.z = fmaxf(fmaf(v.z, s, b.z), 0.f);
    r.w = fmaxf(fmaf(v.w, s, b.w), 0.f);
    ((float4*)h)[idx] = r;
}

// z = relu(agg[:, :128]*in + b2) + noise * exp(agg[:, 128:]*in + b3)
__global__ void k_epilogue_z(const float* __restrict__ b2, const float* __restrict__ b3,
                             const float* __restrict__ noise, float* __restrict__ z) {
    int idx = blockIdx.x * blockDim.x + threadIdx.x;   // float4 index over NN*128/4
    if (idx >= NN * (DOUT / 4)) return;
    int n  = idx >> 5;
    int c4 = idx & 31;
    float s = g_innorm[n];
    const float4* aggrow = (const float4*)(g_agg + (size_t)n * DHID);
    float4 m  = aggrow[c4];
    float4 l  = aggrow[c4 + 32];
    float4 bm = ((const float4*)b2)[c4];
    float4 bl = ((const float4*)b3)[c4];
    float4 nv = ((const float4*)noise)[idx];
    float4 r;
    r.x = fmaxf(fmaf(m.x, s, bm.x), 0.f) + nv.x * expf(fmaf(l.x, s, bl.x));
    r.y = fmaxf(fmaf(m.y, s, bm.y), 0.f) + nv.y * expf(fmaf(l.y, s, bl.y));
    r.z = fmaxf(fmaf(m.z, s, bm.z), 0.f) + nv.z * expf(fmaf(l.z, s, bl.z));
    r.w = fmaxf(fmaf(m.w, s, bm.w), 0.f) + nv.w * expf(fmaf(l.w, s, bl.w));
    ((float4*)z)[idx] = r;
}

// ---------------- launch ----------------
extern "C" void kernel_launch(void* const* d_in, const int* in_sizes, int n_in,
                              void* d_out, int out_size)
{
    const float* features = (const float*)d_in[0];
    const float* noise    = (const float*)d_in[1];
    const float* W1       = (const float*)d_in[2];
    const float* b1       = (const float*)d_in[3];
    const float* W2       = (const float*)d_in[4];
    const float* b2       = (const float*)d_in[5];
    const float* W3       = (const float*)d_in[6];
    const float* b3       = (const float*)d_in[7];
    const float* fcW      = (const float*)d_in[8];
    const int*   src      = (const int*)d_in[9];
    const int*   dst      = (const int*)d_in[10];

    float* out     = (float*)d_out;
    float* z_out   = out;                                 // [NN, 128]
    float* h_out   = out + (size_t)NN * DOUT;             // [NN, 256]
    float* seq_out = h_out + (size_t)NN * DHID;           // [NN, 256]

    float *pt, *pon;
    cudaGetSymbolAddress((void**)&pt,  g_t);
    cudaGetSymbolAddress((void**)&pon, g_outnorm);

    const int T = 256;
    // degrees + norms
    k_zero_norms<<<(NN + T - 1) / T, T>>>();
    k_degree<<<(NE + T - 1) / T, T>>>(src, dst);
    k_fin_norms<<<(NN + T - 1) / T, T>>>();

    dim3 ggrid(2, (NN + 127) / 128);

    // layer 1: t = (features * out_norm) @ W1 ; agg = scatter ; h = relu(agg*in + b1)
    k_gemm<0, 0><<<ggrid, T>>>(features, pon, W1, nullptr, pt, NN, DHID, DIN);
    k_zero_agg<<<(NN * (DHID / 4) + T - 1) / T, T>>>();
    k_scatter<<<NE / 8, T>>>(pt, src, dst);
    k_epilogue_h<<<(NN * (DHID / 4) + T - 1) / T, T>>>(b1, h_out);

    // layer 2: t = (h * out_norm) @ [W2 | W3] ; agg = scatter ; z epilogue
    k_gemm<0, 1><<<ggrid, T>>>(h_out, pon, W2, W3, pt, NN, DHID, DHID);
    k_zero_agg<<<(NN * (DHID / 4) + T - 1) / T, T>>>();
    k_scatter<<<NE / 8, T>>>(pt, src, dst);
    k_epilogue_z<<<(NN * (DOUT / 4) + T - 1) / T, T>>>(b2, b3, noise, z_out);

    // seq_fts = features @ fcW^T
    k_gemm<1, 0><<<ggrid, T>>>(features, nullptr, fcW, nullptr, seq_out, NN, DIN, DIN);
}

// round 2
// speedup vs baseline: 1.5734x; 1.5734x over previous
#include <cuda_runtime.h>
#include <cuda_bf16.h>
#include <cstddef>

#define NN   50000
#define NE   800000
#define DIN  256
#define DHID 256
#define DOUT 128

// ---------------- scratch (device globals; no allocation allowed) ----------------
__device__ float g_outnorm[NN];
__device__ float g_innorm[NN];
__device__ float g_t[(size_t)NN * DHID];    // pre-aggregation transformed features
__device__ float g_agg[(size_t)NN * DHID];  // aggregation accumulator

// ---------------- degree / norm kernels ----------------
__global__ void k_zero_norms() {
    int i = blockIdx.x * blockDim.x + threadIdx.x;
    if (i < NN) { g_outnorm[i] = 0.f; g_innorm[i] = 0.f; }
}

__global__ void k_degree(const int* __restrict__ src, const int* __restrict__ dst) {
    int e = blockIdx.x * blockDim.x + threadIdx.x;
    if (e < NE) {
        atomicAdd(&g_outnorm[src[e]], 1.f);
        atomicAdd(&g_innorm[dst[e]], 1.f);
    }
}

__global__ void k_fin_norms() {
    int i = blockIdx.x * blockDim.x + threadIdx.x;
    if (i < NN) {
        g_outnorm[i] = rsqrtf(fmaxf(g_outnorm[i], 1.f));
        g_innorm[i]  = rsqrtf(fmaxf(g_innorm[i], 1.f));
    }
}

__global__ void k_zero_agg() {
    int i = blockIdx.x * blockDim.x + threadIdx.x;
    if (i < NN * (DHID / 4))
        ((float4*)g_agg)[i] = make_float4(0.f, 0.f, 0.f, 0.f);
}

// ---------------- edge scatter (SpMM): agg[dst] += t[src] ----------------
__device__ __forceinline__ void red_add_v4(float* addr, float4 v) {
    asm volatile("red.global.add.v4.f32 [%0], {%1, %2, %3, %4};"
                 :: "l"(addr), "f"(v.x), "f"(v.y), "f"(v.z), "f"(v.w)
                 : "memory");
}

__global__ void k_scatter(const float* __restrict__ t,
                          const int* __restrict__ src, const int* __restrict__ dst) {
    int w    = (blockIdx.x * blockDim.x + threadIdx.x) >> 5;
    int lane = threadIdx.x & 31;
    if (w >= NE) return;
    int s = src[w];
    int d = dst[w];
    const float4* ts = (const float4*)(t + (size_t)s * DHID);
    float*        ad = g_agg + (size_t)d * DHID;
    float4 v0 = ts[lane];
    float4 v1 = ts[lane + 32];
    red_add_v4(ad + lane * 4, v0);
    red_add_v4(ad + (lane + 32) * 4, v1);
}

// ---------------- GEMM: C[M,Ncols] = (A * rowscale) @ B ----------------
// TRANSB=0: B element (k,n) = B[k*ld + n]; SPLITB: cols [0,128)->B0, [128,256)->B1 (ld=DOUT)
// TRANSB=1: B element (k,n) = B0[n*K + k]
template<int TRANSB, int SPLITB>
__global__ void __launch_bounds__(256, 2)
k_gemm(const float* __restrict__ A, const float* __restrict__ rowscale,
       const float* __restrict__ B0, const float* __restrict__ B1,
       float* __restrict__ C, int M, int Ncols, int K)
{
    constexpr int BM = 128, BN = 128, BK = 8;
    __shared__ float As[BK][BM + 4];
    __shared__ float Bs[BK][BN + 4];

    const int tid  = threadIdx.x;
    const int row0 = blockIdx.y * BM;
    const int col0 = blockIdx.x * BN;
    const int tx   = tid & 15;
    const int ty   = tid >> 4;

    float acc[8][8];
#pragma unroll
    for (int i = 0; i < 8; i++)
#pragma unroll
        for (int j = 0; j < 8; j++) acc[i][j] = 0.f;

    // A tile load mapping: one float4 per thread
    const int am = tid >> 1;
    const int ak = (tid & 1) * 4;
    const bool avalid = (row0 + am) < M;
    const float* Ap = A + (size_t)(row0 + am) * K + ak;
    float ascale = 1.f;
    if (avalid && rowscale) ascale = rowscale[row0 + am];

    // B tile load mapping
    const float* Bp;
    int bstep, bn, bk;
    if constexpr (TRANSB) {
        bn = tid >> 1;
        bk = (tid & 1) * 4;
        Bp = B0 + (size_t)(col0 + bn) * K + bk;
        bstep = BK;
    } else {
        bk = tid >> 5;
        bn = (tid & 31) * 4;
        if constexpr (SPLITB) {
            const float* Bsel = (col0 == 0) ? B0 : B1;
            Bp = Bsel + (size_t)bk * DOUT + bn;
            bstep = BK * DOUT;
        } else {
            Bp = B0 + (size_t)bk * Ncols + col0 + bn;
            bstep = BK * Ncols;
        }
    }

    for (int k0 = 0; k0 < K; k0 += BK) {
        float4 av = make_float4(0.f, 0.f, 0.f, 0.f);
        if (avalid) av = *(const float4*)Ap;
        As[ak + 0][am] = av.x * ascale;
        As[ak + 1][am] = av.y * ascale;
        As[ak + 2][am] = av.z * ascale;
        As[ak + 3][am] = av.w * ascale;
        if constexpr (TRANSB) {
            float4 bv = *(const float4*)Bp;
            Bs[bk + 0][bn] = bv.x;
            Bs[bk + 1][bn] = bv.y;
            Bs[bk + 2][bn] = bv.z;
            Bs[bk + 3][bn] = bv.w;
        } else {
            *(float4*)&Bs[bk][bn] = *(const float4*)Bp;
        }
        __syncthreads();

#pragma unroll
        for (int kk = 0; kk < BK; kk++) {
            float4 a0  = *(const float4*)&As[kk][ty * 8];
            float4 a1  = *(const float4*)&As[kk][ty * 8 + 4];
            float4 bv0 = *(const float4*)&Bs[kk][tx * 8];
            float4 bv1 = *(const float4*)&Bs[kk][tx * 8 + 4];
            float a[8] = {a0.x, a0.y, a0.z, a0.w, a1.x, a1.y, a1.z, a1.w};
            float b[8] = {bv0.x, bv0.y, bv0.z, bv0.w, bv1.x, bv1.y, bv1.z, bv1.w};
#pragma unroll
            for (int i = 0; i < 8; i++)
#pragma unroll
                for (int j = 0; j < 8; j++)
                    acc[i][j] += a[i] * b[j];
        }
        __syncthreads();
        Ap += BK;
        Bp += bstep;
    }

#pragma unroll
    for (int i = 0; i < 8; i++) {
        int row = row0 + ty * 8 + i;
        if (row < M) {
            float* cp = C + (size_t)row * Ncols + col0 + tx * 8;
            *(float4*)cp       = make_float4(acc[i][0], acc[i][1], acc[i][2], acc[i][3]);
            *(float4*)(cp + 4) = make_float4(acc[i][4], acc[i][5], acc[i][6], acc[i][7]);
        }
    }
}

// ---------------- epilogues ----------------
// h = relu(agg * in_norm + b1)
__global__ void k_epilogue_h(const float* __restrict__ b1, float* __restrict__ h) {
    int idx = blockIdx.x * blockDim.x + threadIdx.x;   // float4 index over NN*256/4
    if (idx >= NN * (DHID / 4)) return;
    int n  = idx >> 6;
    int c4 = idx & 63;
    float s  = g_innorm[n];
    float4 v = ((const float4*)g_agg)[idx];
    float4 b = ((const float4*)b1)[c4];
    float4 r;
    r.x = fmaxf(fmaf(v.x, s, b.x), 0.f);
    r.y = fmaxf(fmaf(v.y, s, b.y), 0.f);
    r.z = fmaxf(fmaf(v.z, s, b.z), 0.f);
    r.w = fmaxf(fmaf(v.w, s, b.w), 0.f);
    ((float4*)h)[idx] = r;
}

// z = relu(agg[:, :128]*in + b2) + noise * exp(agg[:, 128:]*in + b3)
__global__ void k_epilogue_z(const float* __restrict__ b2, const float* __restrict__ b3,
                             const float* __restrict__ noise, float* __restrict__ z) {
    int idx = blockIdx.x * blockDim.x + threadIdx.x;   // float4 index over NN*128/4
    if (idx >= NN * (DOUT / 4)) return;
    int n  = idx >> 5;
    int c4 = idx & 31;
    float s = g_innorm[n];
    const float4* aggrow = (const float4*)(g_agg + (size_t)n * DHID);
    float4 m  = aggrow[c4];
    float4 l  = aggrow[c4 + 32];
    float4 bm = ((const float4*)b2)[c4];
    float4 bl = ((const float4*)b3)[c4];
    float4 nv = ((const float4*)noise)[idx];
    float4 r;
    r.x = fmaxf(fmaf(m.x, s, bm.x), 0.f) + nv.x * expf(fmaf(l.x, s, bl.x));
    r.y = fmaxf(fmaf(m.y, s, bm.y), 0.f) + nv.y * expf(fmaf(l.y, s, bl.y));
    r.z = fmaxf(fmaf(m.z, s, bm.z), 0.f) + nv.z * expf(fmaf(l.z, s, bl.z));
    r.w = fmaxf(fmaf(m.w, s, bm.w), 0.f) + nv.w * expf(fmaf(l.w, s, bl.w));
    ((float4*)z)[idx] = r;
}

// ---------------- launch ----------------
extern "C" void kernel_launch(void* const* d_in, const int* in_sizes, int n_in,
                              void* d_out, int out_size)
{
    const float* features = (const float*)d_in[0];
    const float* noise    = (const float*)d_in[1];
    const float* W1       = (const float*)d_in[2];
    const float* b1       = (const float*)d_in[3];
    const float* W2       = (const float*)d_in[4];
    const float* b2       = (const float*)d_in[5];
    const float* W3       = (const float*)d_in[6];
    const float* b3       = (const float*)d_in[7];
    const float* fcW      = (const float*)d_in[8];
    const int*   src      = (const int*)d_in[9];
    const int*   dst      = (const int*)d_in[10];

    float* out     = (float*)d_out;
    float* z_out   = out;                                 // [NN, 128]
    float* h_out   = out + (size_t)NN * DOUT;             // [NN, 256]
    float* seq_out = h_out + (size_t)NN * DHID;           // [NN, 256]

    float *pt, *pon;
    cudaGetSymbolAddress((void**)&pt,  g_t);
    cudaGetSymbolAddress((void**)&pon, g_outnorm);

    const int T = 256;
    // degrees + norms
    k_zero_norms<<<(NN + T - 1) / T, T>>>();
    k_degree<<<(NE + T - 1) / T, T>>>(src, dst);
    k_fin_norms<<<(NN + T - 1) / T, T>>>();

    dim3 ggrid(2, (NN + 127) / 128);

    // layer 1: t = (features * out_norm) @ W1 ; agg = scatter ; h = relu(agg*in + b1)
    k_gemm<0, 0><<<ggrid, T>>>(features, pon, W1, nullptr, pt, NN, DHID, DIN);
    k_zero_agg<<<(NN * (DHID / 4) + T - 1) / T, T>>>();
    k_scatter<<<NE / 8, T>>>(pt, src, dst);
    k_epilogue_h<<<(NN * (DHID / 4) + T - 1) / T, T>>>(b1, h_out);

    // layer 2: t = (h * out_norm) @ [W2 | W3] ; agg = scatter ; z epilogue
    k_gemm<0, 1><<<ggrid, T>>>(h_out, pon, W2, W3, pt, NN, DHID, DHID);
    k_zero_agg<<<(NN * (DHID / 4) + T - 1) / T, T>>>();
    k_scatter<<<NE / 8, T>>>(pt, src, dst);
    k_epilogue_z<<<(NN * (DOUT / 4) + T - 1) / T, T>>>(b2, b3, noise, z_out);

    // seq_fts = features @ fcW^T
    k_gemm<1, 0><<<ggrid, T>>>(features, nullptr, fcW, nullptr, seq_out, NN, DIN, DIN);
}

// round 3
// speedup vs baseline: 2.5755x; 1.6369x over previous
#include <cuda_runtime.h>
#include <cuda_bf16.h>
#include <cstdint>
#include <cstddef>

#define NN   50000
#define NE   800000
#define DIN  256
#define DHID 256
#define DOUT 128

// ---------------- scratch (device globals; no allocation allowed) ----------------
__device__ float g_outnorm[NN];
__device__ float g_innorm[NN];
__device__ float g_t[(size_t)NN * DHID];    // pre-aggregation transformed features
__device__ float g_agg[(size_t)NN * DHID];  // aggregation accumulator

// ---------------- degree / norm kernels ----------------
__global__ void k_zero_norms() {
    int i = blockIdx.x * blockDim.x + threadIdx.x;
    if (i < NN) { g_outnorm[i] = 0.f; g_innorm[i] = 0.f; }
}

__global__ void k_degree(const int* __restrict__ src, const int* __restrict__ dst) {
    int e = blockIdx.x * blockDim.x + threadIdx.x;
    if (e < NE) {
        atomicAdd(&g_outnorm[src[e]], 1.f);
        atomicAdd(&g_innorm[dst[e]], 1.f);
    }
}

__global__ void k_fin_norms() {
    int i = blockIdx.x * blockDim.x + threadIdx.x;
    if (i < NN) {
        g_outnorm[i] = rsqrtf(fmaxf(g_outnorm[i], 1.f));
        g_innorm[i]  = rsqrtf(fmaxf(g_innorm[i], 1.f));
    }
}

__global__ void k_zero_agg() {
    int i = blockIdx.x * blockDim.x + threadIdx.x;
    if (i < NN * (DHID / 4))
        ((float4*)g_agg)[i] = make_float4(0.f, 0.f, 0.f, 0.f);
}

// ---------------- edge scatter (SpMM): agg[dst] += t[src] ----------------
__device__ __forceinline__ void red_add_v4(float* addr, float4 v) {
    asm volatile("red.global.add.v4.f32 [%0], {%1, %2, %3, %4};"
                 :: "l"(addr), "f"(v.x), "f"(v.y), "f"(v.z), "f"(v.w)
                 : "memory");
}

__global__ void k_scatter(const float* __restrict__ t,
                          const int* __restrict__ src, const int* __restrict__ dst) {
    int w    = (blockIdx.x * blockDim.x + threadIdx.x) >> 5;
    int lane = threadIdx.x & 31;
    if (w >= NE) return;
    int s = src[w];
    int d = dst[w];
    const float4* ts = (const float4*)(t + (size_t)s * DHID);
    float*        ad = g_agg + (size_t)d * DHID;
    float4 v0 = ts[lane];
    float4 v1 = ts[lane + 32];
    red_add_v4(ad + lane * 4, v0);
    red_add_v4(ad + (lane + 32) * 4, v1);
}

// ---------------- tf32 helpers ----------------
__device__ __forceinline__ uint32_t f2tf32(float x) {
    uint32_t r;
    asm("cvt.rna.tf32.f32 %0, %1;" : "=r"(r) : "f"(x));
    return r;
}

__device__ __forceinline__ void mma_tf32(float* c, const uint32_t* a, const uint32_t* b) {
    asm volatile(
        "mma.sync.aligned.m16n8k8.row.col.f32.tf32.tf32.f32 "
        "{%0,%1,%2,%3}, {%4,%5,%6,%7}, {%8,%9}, {%0,%1,%2,%3};"
        : "+f"(c[0]), "+f"(c[1]), "+f"(c[2]), "+f"(c[3])
        : "r"(a[0]), "r"(a[1]), "r"(a[2]), "r"(a[3]), "r"(b[0]), "r"(b[1]));
}

// ---------------- tensor-core GEMM: C[M,Ncols] = (A * rowscale) @ B ----------------
// TRANSB=0: B(k,n) = B[k*ld + n]; SPLITB: cols [0,128)->B0, [128,256)->B1 (ld=DOUT)
// TRANSB=1: B(k,n) = B0[n*K + k]
template<int TRANSB, int SPLITB>
__global__ void __launch_bounds__(256, 2)
k_gemm_mma(const float* __restrict__ A, const float* __restrict__ rowscale,
           const float* __restrict__ B0, const float* __restrict__ B1,
           float* __restrict__ C, int M, int Ncols, int K)
{
    constexpr int BM = 128, BN = 128, BK = 32;
    // A fragment-friendly: As4[k/4][m][4] (pad m by 1 row-group)
    __shared__ uint32_t As4[BK / 4][BM + 1][4];
    __shared__ uint32_t Bs[BK][BN + 8];

    const int tid  = threadIdx.x;
    const int lane = tid & 31;
    const int warp = tid >> 5;
    const int row0 = blockIdx.y * BM;
    const int col0 = blockIdx.x * BN;
    const int warpM = (warp >> 2) * 64;   // 2 warps over M
    const int warpN = (warp & 3) * 32;    // 4 warps over N

    float acc[4][4][4];
#pragma unroll
    for (int i = 0; i < 4; i++)
#pragma unroll
        for (int j = 0; j < 4; j++)
#pragma unroll
            for (int r = 0; r < 4; r++) acc[i][j][r] = 0.f;

    // ---- A staging mapping: thread covers row (tid>>3)+32*it, k quad (tid&7)
    const int arow = tid >> 3;
    const int ak4  = tid & 7;
    bool avalid[4];
    const float* aptr[4];
    float ascale[4];
#pragma unroll
    for (int it = 0; it < 4; it++) {
        int gr = row0 + arow + it * 32;
        avalid[it] = gr < M;
        aptr[it]   = A + (size_t)(avalid[it] ? gr : 0) * K + ak4 * 4;
        ascale[it] = (avalid[it] && rowscale) ? rowscale[gr] : 1.f;
    }

    // ---- B staging mapping
    const float* bptr;          // non-trans base
    int bldb = 0;
    const int bn4 = tid & 31;   // non-trans: float4 column
    const int bk  = tid >> 5;   // non-trans: k row (0..7, step 8)
    const int tkq = tid & 7;    // trans: k quad
    const int tn  = tid >> 3;   // trans: n row (0..31, step 32)
    if constexpr (TRANSB) {
        bptr = B0;              // fcW: [Ncols][K]
    } else if constexpr (SPLITB) {
        bptr = ((col0 == 0) ? B0 : B1);
        bldb = DOUT;
    } else {
        bptr = B0 + col0;
        bldb = Ncols;
    }

    for (int k0 = 0; k0 < K; k0 += BK) {
        // stage A (tf32, rowscaled)
#pragma unroll
        for (int it = 0; it < 4; it++) {
            float4 v = make_float4(0.f, 0.f, 0.f, 0.f);
            if (avalid[it]) v = *(const float4*)(aptr[it] + k0);
            uint4 t;
            t.x = f2tf32(v.x * ascale[it]);
            t.y = f2tf32(v.y * ascale[it]);
            t.z = f2tf32(v.z * ascale[it]);
            t.w = f2tf32(v.w * ascale[it]);
            *(uint4*)&As4[ak4][arow + it * 32][0] = t;
        }
        // stage B (tf32)
        if constexpr (TRANSB) {
#pragma unroll
            for (int it = 0; it < 4; it++) {
                int n = tn + it * 32;
                float4 v = *(const float4*)(bptr + (size_t)(col0 + n) * K + k0 + tkq * 4);
                Bs[tkq * 4 + 0][n] = f2tf32(v.x);
                Bs[tkq * 4 + 1][n] = f2tf32(v.y);
                Bs[tkq * 4 + 2][n] = f2tf32(v.z);
                Bs[tkq * 4 + 3][n] = f2tf32(v.w);
            }
        } else {
#pragma unroll
            for (int it = 0; it < 4; it++) {
                int k = bk + it * 8;
                float4 v = *(const float4*)(bptr + (size_t)(k0 + k) * bldb + bn4 * 4);
                uint4 t;
                t.x = f2tf32(v.x);
                t.y = f2tf32(v.y);
                t.z = f2tf32(v.z);
                t.w = f2tf32(v.w);
                *(uint4*)&Bs[k][bn4 * 4] = t;
            }
        }
        __syncthreads();

#pragma unroll
        for (int ks = 0; ks < 4; ks++) {            // kstep = ks*8
            uint32_t a[4][4], b[4][2];
#pragma unroll
            for (int mi = 0; mi < 4; mi++) {
                const uint32_t* ap = &As4[ks * 2][warpM + mi * 16 + (lane >> 2)][lane & 3];
                a[mi][0] = ap[0];
                a[mi][1] = ap[8 * 4];                 // +8 rows
                a[mi][2] = ap[(BM + 1) * 4];          // next k quad
                a[mi][3] = ap[(BM + 1) * 4 + 8 * 4];
            }
#pragma unroll
            for (int ni = 0; ni < 4; ni++) {
                const uint32_t* bp = &Bs[ks * 8 + (lane & 3)][warpN + ni * 8 + (lane >> 2)];
                b[ni][0] = bp[0];
                b[ni][1] = bp[4 * (BN + 8)];          // +4 k rows
            }
#pragma unroll
            for (int mi = 0; mi < 4; mi++)
#pragma unroll
                for (int ni = 0; ni < 4; ni++)
                    mma_tf32(acc[mi][ni], a[mi], b[ni]);
        }
        __syncthreads();
    }

    // ---- epilogue: write fp32
#pragma unroll
    for (int mi = 0; mi < 4; mi++) {
        int gr0 = row0 + warpM + mi * 16 + (lane >> 2);
#pragma unroll
        for (int ni = 0; ni < 4; ni++) {
            int col = col0 + warpN + ni * 8 + (lane & 3) * 2;
            if (gr0 < M)
                *(float2*)(C + (size_t)gr0 * Ncols + col) = make_float2(acc[mi][ni][0], acc[mi][ni][1]);
            if (gr0 + 8 < M)
                *(float2*)(C + (size_t)(gr0 + 8) * Ncols + col) = make_float2(acc[mi][ni][2], acc[mi][ni][3]);
        }
    }
}

// ---------------- epilogues ----------------
// h = relu(agg * in_norm + b1)
__global__ void k_epilogue_h(const float* __restrict__ b1, float* __restrict__ h) {
    int idx = blockIdx.x * blockDim.x + threadIdx.x;   // float4 index over NN*256/4
    if (idx >= NN * (DHID / 4)) return;
    int n  = idx >> 6;
    int c4 = idx & 63;
    float s  = g_innorm[n];
    float4 v = ((const float4*)g_agg)[idx];
    float4 b = ((const float4*)b1)[c4];
    float4 r;
    r.x = fmaxf(fmaf(v.x, s, b.x), 0.f);
    r.y = fmaxf(fmaf(v.y, s, b.y), 0.f);
    r.z = fmaxf(fmaf(v.z, s, b.z), 0.f);
    r.w = fmaxf(fmaf(v.w, s, b.w), 0.f);
    ((float4*)h)[idx] = r;
}

// z = relu(agg[:, :128]*in + b2) + noise * exp(agg[:, 128:]*in + b3)
__global__ void k_epilogue_z(const float* __restrict__ b2, const float* __restrict__ b3,
                             const float* __restrict__ noise, float* __restrict__ z) {
    int idx = blockIdx.x * blockDim.x + threadIdx.x;   // float4 index over NN*128/4
    if (idx >= NN * (DOUT / 4)) return;
    int n  = idx >> 5;
    int c4 = idx & 31;
    float s = g_innorm[n];
    const float4* aggrow = (const float4*)(g_agg + (size_t)n * DHID);
    float4 m  = aggrow[c4];
    float4 l  = aggrow[c4 + 32];
    float4 bm = ((const float4*)b2)[c4];
    float4 bl = ((const float4*)b3)[c4];
    float4 nv = ((const float4*)noise)[idx];
    float4 r;
    r.x = fmaxf(fmaf(m.x, s, bm.x), 0.f) + nv.x * expf(fmaf(l.x, s, bl.x));
    r.y = fmaxf(fmaf(m.y, s, bm.y), 0.f) + nv.y * expf(fmaf(l.y, s, bl.y));
    r.z = fmaxf(fmaf(m.z, s, bm.z), 0.f) + nv.z * expf(fmaf(l.z, s, bl.z));
    r.w = fmaxf(fmaf(m.w, s, bm.w), 0.f) + nv.w * expf(fmaf(l.w, s, bl.w));
    ((float4*)z)[idx] = r;
}

// ---------------- launch ----------------
extern "C" void kernel_launch(void* const* d_in, const int* in_sizes, int n_in,
                              void* d_out, int out_size)
{
    const float* features = (const float*)d_in[0];
    const float* noise    = (const float*)d_in[1];
    const float* W1       = (const float*)d_in[2];
    const float* b1       = (const float*)d_in[3];
    const float* W2       = (const float*)d_in[4];
    const float* b2       = (const float*)d_in[5];
    const float* W3       = (const float*)d_in[6];
    const float* b3       = (const float*)d_in[7];
    const float* fcW      = (const float*)d_in[8];
    const int*   src      = (const int*)d_in[9];
    const int*   dst      = (const int*)d_in[10];

    float* out     = (float*)d_out;
    float* z_out   = out;                                 // [NN, 128]
    float* h_out   = out + (size_t)NN * DOUT;             // [NN, 256]
    float* seq_out = h_out + (size_t)NN * DHID;           // [NN, 256]

    float *pt, *pon;
    cudaGetSymbolAddress((void**)&pt,  g_t);
    cudaGetSymbolAddress((void**)&pon, g_outnorm);

    const int T = 256;
    // degrees + norms
    k_zero_norms<<<(NN + T - 1) / T, T>>>();
    k_degree<<<(NE + T - 1) / T, T>>>(src, dst);
    k_fin_norms<<<(NN + T - 1) / T, T>>>();

    dim3 ggrid(2, (NN + 127) / 128);

    // layer 1: t = (features * out_norm) @ W1 ; agg = scatter ; h = relu(agg*in + b1)
    k_gemm_mma<0, 0><<<ggrid, T>>>(features, pon, W1, nullptr, pt, NN, DHID, DIN);
    k_zero_agg<<<(NN * (DHID / 4) + T - 1) / T, T>>>();
    k_scatter<<<NE / 8, T>>>(pt, src, dst);
    k_epilogue_h<<<(NN * (DHID / 4) + T - 1) / T, T>>>(b1, h_out);

    // layer 2: t = (h * out_norm) @ [W2 | W3] ; agg = scatter ; z epilogue
    k_gemm_mma<0, 1><<<ggrid, T>>>(h_out, pon, W2, W3, pt, NN, DHID, DHID);
    k_zero_agg<<<(NN * (DHID / 4) + T - 1) / T, T>>>();
    k_scatter<<<NE / 8, T>>>(pt, src, dst);
    k_epilogue_z<<<(NN * (DOUT / 4) + T - 1) / T, T>>>(b2, b3, noise, z_out);

    // seq_fts = features @ fcW^T
    k_gemm_mma<1, 0><<<ggrid, T>>>(features, nullptr, fcW, nullptr, seq_out, NN, DIN, DIN);
}

// round 4
// speedup vs baseline: 4.0917x; 1.5887x over previous
#include <cuda_runtime.h>
#include <cuda_bf16.h>
#include <cstdint>
#include <cstddef>

#define NN   50000
#define NE   800000
#define DIN  256
#define DHID 256
#define DOUT 128

// ---------------- scratch (device globals; no allocation allowed) ----------------
__device__ float g_outnorm[NN];
__device__ float g_innorm[NN];
__device__ int   g_outc[NN];
__device__ int   g_inc[NN];
__device__ int   g_rowptr[NN + 1];
__device__ int   g_cursor[NN];
__device__ int   g_csrc[NE];                 // src node per CSR slot (grouped by dst)
__device__ float g_t[(size_t)NN * DHID];     // pre-aggregation transformed features

// ---------------- degree / norm / CSR kernels ----------------
__global__ void k_zero_counts() {
    int i = blockIdx.x * blockDim.x + threadIdx.x;
    if (i < NN) { g_outc[i] = 0; g_inc[i] = 0; }
}

__global__ void k_degree(const int* __restrict__ src, const int* __restrict__ dst) {
    int e = blockIdx.x * blockDim.x + threadIdx.x;
    if (e < NE) {
        atomicAdd(&g_outc[src[e]], 1);
        atomicAdd(&g_inc[dst[e]], 1);
    }
}

__global__ void k_fin_norms() {
    int i = blockIdx.x * blockDim.x + threadIdx.x;
    if (i < NN) {
        g_outnorm[i] = rsqrtf(fmaxf((float)g_outc[i], 1.f));
        g_innorm[i]  = rsqrtf(fmaxf((float)g_inc[i], 1.f));
    }
}

// single-block exclusive scan of g_inc -> g_rowptr / g_cursor
__global__ void k_scan() {
    __shared__ int wsum[32];
    __shared__ int s_carry;
    const int tid = threadIdx.x, lane = tid & 31, wid = tid >> 5;
    if (tid == 0) s_carry = 0;
    __syncthreads();
    for (int base = 0; base < NN; base += 1024) {
        int i = base + tid;
        int v = (i < NN) ? g_inc[i] : 0;
        int x = v;
#pragma unroll
        for (int o = 1; o < 32; o <<= 1) {
            int y = __shfl_up_sync(0xffffffffu, x, o);
            if (lane >= o) x += y;
        }
        if (lane == 31) wsum[wid] = x;
        __syncthreads();
        if (wid == 0) {
            int w = wsum[lane];
            int xs = w;
#pragma unroll
            for (int o = 1; o < 32; o <<= 1) {
                int y = __shfl_up_sync(0xffffffffu, xs, o);
                if (lane >= o) xs += y;
            }
            wsum[lane] = xs;
        }
        __syncthreads();
        int carry = s_carry;
        int excl = carry + (wid > 0 ? wsum[wid - 1] : 0) + x - v;
        if (i < NN) { g_rowptr[i] = excl; g_cursor[i] = excl; }
        __syncthreads();
        if (tid == 1023) s_carry = carry + wsum[31];
        __syncthreads();
    }
    if (threadIdx.x == 0) g_rowptr[NN] = s_carry;
}

__global__ void k_csr_fill(const int* __restrict__ src, const int* __restrict__ dst) {
    int e = blockIdx.x * blockDim.x + threadIdx.x;
    if (e < NE) {
        int pos = atomicAdd(&g_cursor[dst[e]], 1);
        g_csrc[pos] = src[e];
    }
}

// ---------------- gather SpMM + fused epilogues ----------------
__device__ __forceinline__ void acc_add(float4& a, const float4 b) {
    a.x += b.x; a.y += b.y; a.z += b.z; a.w += b.w;
}

// h = relu(in_norm * sum_{src in N(dst)} t[src] + b1)
__global__ void k_gather_h(const float* __restrict__ t, const float* __restrict__ b1,
                           float* __restrict__ h) {
    int node = (blockIdx.x * blockDim.x + threadIdx.x) >> 5;
    int lane = threadIdx.x & 31;
    if (node >= NN) return;
    int beg = g_rowptr[node], end = g_rowptr[node + 1];
    float4 a0 = make_float4(0.f, 0.f, 0.f, 0.f);
    float4 a1 = make_float4(0.f, 0.f, 0.f, 0.f);
    int j = beg;
    for (; j + 1 < end; j += 2) {
        int s0 = g_csrc[j], s1 = g_csrc[j + 1];
        const float4* r0 = (const float4*)(t + (size_t)s0 * DHID);
        const float4* r1 = (const float4*)(t + (size_t)s1 * DHID);
        float4 v00 = r0[lane], v01 = r0[lane + 32];
        float4 v10 = r1[lane], v11 = r1[lane + 32];
        acc_add(a0, v00); acc_add(a1, v01);
        acc_add(a0, v10); acc_add(a1, v11);
    }
    if (j < end) {
        const float4* r = (const float4*)(t + (size_t)g_csrc[j] * DHID);
        acc_add(a0, r[lane]); acc_add(a1, r[lane + 32]);
    }
    float s = g_innorm[node];
    float4 bb0 = ((const float4*)b1)[lane];
    float4 bb1 = ((const float4*)b1)[lane + 32];
    float4 o0, o1;
    o0.x = fmaxf(fmaf(a0.x, s, bb0.x), 0.f); o0.y = fmaxf(fmaf(a0.y, s, bb0.y), 0.f);
    o0.z = fmaxf(fmaf(a0.z, s, bb0.z), 0.f); o0.w = fmaxf(fmaf(a0.w, s, bb0.w), 0.f);
    o1.x = fmaxf(fmaf(a1.x, s, bb1.x), 0.f); o1.y = fmaxf(fmaf(a1.y, s, bb1.y), 0.f);
    o1.z = fmaxf(fmaf(a1.z, s, bb1.z), 0.f); o1.w = fmaxf(fmaf(a1.w, s, bb1.w), 0.f);
    float4* hp = (float4*)(h + (size_t)node * DHID);
    hp[lane] = o0;
    hp[lane + 32] = o1;
}

// z = relu(agg[:, :128]*in + b2) + noise * exp(agg[:, 128:]*in + b3)
__global__ void k_gather_z(const float* __restrict__ t, const float* __restrict__ b2,
                           const float* __restrict__ b3, const float* __restrict__ noise,
                           float* __restrict__ z) {
    int node = (blockIdx.x * blockDim.x + threadIdx.x) >> 5;
    int lane = threadIdx.x & 31;
    if (node >= NN) return;
    int beg = g_rowptr[node], end = g_rowptr[node + 1];
    float4 a0 = make_float4(0.f, 0.f, 0.f, 0.f);   // mean cols
    float4 a1 = make_float4(0.f, 0.f, 0.f, 0.f);   // logstd cols
    int j = beg;
    for (; j + 1 < end; j += 2) {
        int s0 = g_csrc[j], s1 = g_csrc[j + 1];
        const float4* r0 = (const float4*)(t + (size_t)s0 * DHID);
        const float4* r1 = (const float4*)(t + (size_t)s1 * DHID);
        float4 v00 = r0[lane], v01 = r0[lane + 32];
        float4 v10 = r1[lane], v11 = r1[lane + 32];
        acc_add(a0, v00); acc_add(a1, v01);
        acc_add(a0, v10); acc_add(a1, v11);
    }
    if (j < end) {
        const float4* r = (const float4*)(t + (size_t)g_csrc[j] * DHID);
        acc_add(a0, r[lane]); acc_add(a1, r[lane + 32]);
    }
    float s = g_innorm[node];
    float4 bm = ((const float4*)b2)[lane];
    float4 bl = ((const float4*)b3)[lane];
    float4 nv = ((const float4*)(noise + (size_t)node * DOUT))[lane];
    float4 r;
    r.x = fmaxf(fmaf(a0.x, s, bm.x), 0.f) + nv.x * expf(fmaf(a1.x, s, bl.x));
    r.y = fmaxf(fmaf(a0.y, s, bm.y), 0.f) + nv.y * expf(fmaf(a1.y, s, bl.y));
    r.z = fmaxf(fmaf(a0.z, s, bm.z), 0.f) + nv.z * expf(fmaf(a1.z, s, bl.z));
    r.w = fmaxf(fmaf(a0.w, s, bm.w), 0.f) + nv.w * expf(fmaf(a1.w, s, bl.w));
    ((float4*)(z + (size_t)node * DOUT))[lane] = r;
}

// ---------------- tf32 / cp.async helpers ----------------
__device__ __forceinline__ uint32_t f2tf32(float x) {
    uint32_t r;
    asm("cvt.rna.tf32.f32 %0, %1;" : "=r"(r) : "f"(x));
    return r;
}

__device__ __forceinline__ void mma_tf32(float* c, const uint32_t* a, const uint32_t* b) {
    asm volatile(
        "mma.sync.aligned.m16n8k8.row.col.f32.tf32.tf32.f32 "
        "{%0,%1,%2,%3}, {%4,%5,%6,%7}, {%8,%9}, {%0,%1,%2,%3};"
        : "+f"(c[0]), "+f"(c[1]), "+f"(c[2]), "+f"(c[3])
        : "r"(a[0]), "r"(a[1]), "r"(a[2]), "r"(a[3]), "r"(b[0]), "r"(b[1]));
}

__device__ __forceinline__ void cp16(uint32_t dst, const void* src) {
    asm volatile("cp.async.cg.shared.global [%0], [%1], 16;" :: "r"(dst), "l"(src));
}
__device__ __forceinline__ void cp_commit() { asm volatile("cp.async.commit_group;"); }
template<int N>
__device__ __forceinline__ void cp_wait() { asm volatile("cp.async.wait_group %0;" :: "n"(N)); }

// ---------------- tensor-core GEMM (cp.async double-buffered) ----------------
// C[M,Ncols] = (A @ B) * rowscale (applied to output rows; == (A*rowscale) @ B)
// TRANSB=0: B(k,n)=B[k*ld+n]; SPLITB: cols [0,128)->B0, [128,256)->B1 (ld=DOUT)
// TRANSB=1: B(k,n)=B0[n*K+k]
template<int TRANSB, int SPLITB>
__global__ void __launch_bounds__(256, 2)
k_gemm_mma(const float* __restrict__ A, const float* __restrict__ rowscale,
           const float* __restrict__ B0, const float* __restrict__ B1,
           float* __restrict__ C, int M, int Ncols, int K)
{
    constexpr int BM = 128, BN = 128, BK = 16;
    constexpr int ALD = BK + 4;                      // 20 floats/row, 16B-aligned stride
    constexpr int BSZ = TRANSB ? (BN * ALD) : (BK * (BN + 8));
    __shared__ float As[2][BM * ALD];
    __shared__ float Bs[2][BSZ];

    const int tid  = threadIdx.x;
    const int lane = tid & 31;
    const int warp = tid >> 5;
    const int row0 = blockIdx.y * BM;
    const int col0 = blockIdx.x * BN;
    const int warpM = (warp >> 2) * 64;
    const int warpN = (warp & 3) * 32;

    float acc[4][4][4];
#pragma unroll
    for (int i = 0; i < 4; i++)
#pragma unroll
        for (int j = 0; j < 4; j++)
#pragma unroll
            for (int r = 0; r < 4; r++) acc[i][j][r] = 0.f;

    // A-style tile mapping (also used for transposed B): 128 rows x 4 quads
    const int ar = tid >> 2;          // row 0..63 (+64 on 2nd pass)
    const int ak4 = tid & 3;          // k quad
    // B non-trans mapping: 16 rows x 32 quads
    const int bkr = tid >> 5;         // k row 0..7 (+8)
    const int bn4 = tid & 31;         // n quad

    const float* bbase;
    int bld = 0;
    if constexpr (TRANSB) {
        bbase = B0;                   // [Ncols][K]
    } else if constexpr (SPLITB) {
        bbase = (col0 == 0) ? B0 : B1;
        bld = DOUT;
    } else {
        bbase = B0 + col0;
        bld = Ncols;
    }

    auto stage = [&](int k0, int buf) {
        // A tile
#pragma unroll
        for (int i = 0; i < 2; i++) {
            int r = ar + i * 64;
            int gr = row0 + r;
            if (gr >= M) gr = M - 1;                  // clamp; OOB rows never stored
            cp16((uint32_t)__cvta_generic_to_shared(&As[buf][r * ALD + ak4 * 4]),
                 A + (size_t)gr * K + k0 + ak4 * 4);
        }
        // B tile
        if constexpr (TRANSB) {
#pragma unroll
            for (int i = 0; i < 2; i++) {
                int r = ar + i * 64;                  // n index
                cp16((uint32_t)__cvta_generic_to_shared(&Bs[buf][r * ALD + ak4 * 4]),
                     bbase + (size_t)(col0 + r) * K + k0 + ak4 * 4);
            }
        } else {
#pragma unroll
            for (int i = 0; i < 2; i++) {
                int k = bkr + i * 8;
                cp16((uint32_t)__cvta_generic_to_shared(&Bs[buf][k * (BN + 8) + bn4 * 4]),
                     bbase + (size_t)(k0 + k) * bld + bn4 * 4);
            }
        }
    };

    const int NT = K / BK;
    stage(0, 0);
    cp_commit();

    for (int t = 0; t < NT; t++) {
        int buf = t & 1;
        if (t + 1 < NT) {
            stage((t + 1) * BK, buf ^ 1);
            cp_commit();
            cp_wait<1>();
        } else {
            cp_wait<0>();
        }
        __syncthreads();

#pragma unroll
        for (int ks = 0; ks < 2; ks++) {
            uint32_t a[4][4], b[4][2];
#pragma unroll
            for (int mi = 0; mi < 4; mi++) {
                const float* ap = &As[buf][(warpM + mi * 16 + (lane >> 2)) * ALD + ks * 8 + (lane & 3)];
                a[mi][0] = f2tf32(ap[0]);
                a[mi][1] = f2tf32(ap[8 * ALD]);
                a[mi][2] = f2tf32(ap[4]);
                a[mi][3] = f2tf32(ap[8 * ALD + 4]);
            }
#pragma unroll
            for (int ni = 0; ni < 4; ni++) {
                if constexpr (TRANSB) {
                    const float* bp = &Bs[buf][(warpN + ni * 8 + (lane >> 2)) * ALD + ks * 8 + (lane & 3)];
                    b[ni][0] = f2tf32(bp[0]);
                    b[ni][1] = f2tf32(bp[4]);
                } else {
                    const float* bp = &Bs[buf][(ks * 8 + (lane & 3)) * (BN + 8) + warpN + ni * 8 + (lane >> 2)];
                    b[ni][0] = f2tf32(bp[0]);
                    b[ni][1] = f2tf32(bp[4 * (BN + 8)]);
                }
            }
#pragma unroll
            for (int mi = 0; mi < 4; mi++)
#pragma unroll
                for (int ni = 0; ni < 4; ni++)
                    mma_tf32(acc[mi][ni], a[mi], b[ni]);
        }
        __syncthreads();
    }

    // epilogue: apply rowscale to output rows, store fp32
#pragma unroll
    for (int mi = 0; mi < 4; mi++) {
        int gr0 = row0 + warpM + mi * 16 + (lane >> 2);
        float s0 = 1.f, s1 = 1.f;
        if (rowscale) {
            if (gr0 < M)     s0 = rowscale[gr0];
            if (gr0 + 8 < M) s1 = rowscale[gr0 + 8];
        }
#pragma unroll
        for (int ni = 0; ni < 4; ni++) {
            int col = col0 + warpN + ni * 8 + (lane & 3) * 2;
            if (gr0 < M)
                *(float2*)(C + (size_t)gr0 * Ncols + col) =
                    make_float2(acc[mi][ni][0] * s0, acc[mi][ni][1] * s0);
            if (gr0 + 8 < M)
                *(float2*)(C + (size_t)(gr0 + 8) * Ncols + col) =
                    make_float2(acc[mi][ni][2] * s1, acc[mi][ni][3] * s1);
        }
    }
}

// ---------------- launch ----------------
extern "C" void kernel_launch(void* const* d_in, const int* in_sizes, int n_in,
                              void* d_out, int out_size)
{
    const float* features = (const float*)d_in[0];
    const float* noise    = (const float*)d_in[1];
    const float* W1       = (const float*)d_in[2];
    const float* b1       = (const float*)d_in[3];
    const float* W2       = (const float*)d_in[4];
    const float* b2       = (const float*)d_in[5];
    const float* W3       = (const float*)d_in[6];
    const float* b3       = (const float*)d_in[7];
    const float* fcW      = (const float*)d_in[8];
    const int*   src      = (const int*)d_in[9];
    const int*   dst      = (const int*)d_in[10];

    float* out     = (float*)d_out;
    float* z_out   = out;                                 // [NN, 128]
    float* h_out   = out + (size_t)NN * DOUT;             // [NN, 256]
    float* seq_out = h_out + (size_t)NN * DHID;           // [NN, 256]

    float *pt, *pon;
    cudaGetSymbolAddress((void**)&pt,  g_t);
    cudaGetSymbolAddress((void**)&pon, g_outnorm);

    const int T = 256;
    // degrees, norms, CSR by dst
    k_zero_counts<<<(NN + T - 1) / T, T>>>();
    k_degree<<<(NE + T - 1) / T, T>>>(src, dst);
    k_fin_norms<<<(NN + T - 1) / T, T>>>();
    k_scan<<<1, 1024>>>();
    k_csr_fill<<<(NE + T - 1) / T, T>>>(src, dst);

    dim3 ggrid(2, (NN + 127) / 128);
    const int gather_blocks = (NN * 32 + T - 1) / T;

    // layer 1
    k_gemm_mma<0, 0><<<ggrid, T>>>(features, pon, W1, nullptr, pt, NN, DHID, DIN);
    k_gather_h<<<gather_blocks, T>>>(pt, b1, h_out);

    // layer 2 (W2|W3 fused)
    k_gemm_mma<0, 1><<<ggrid, T>>>(h_out, pon, W2, W3, pt, NN, DHID, DHID);
    k_gather_z<<<gather_blocks, T>>>(pt, b2, b3, noise, z_out);

    // seq_fts = features @ fcW^T
    k_gemm_mma<1, 0><<<ggrid, T>>>(features, nullptr, fcW, nullptr, seq_out, NN, DIN, DIN);
}

// round 5
// speedup vs baseline: 4.4706x; 1.0926x over previous
#include <cuda_runtime.h>
#include <cuda_bf16.h>
#include <cstdint>
#include <cstddef>

#define NN   50000
#define NE   800000
#define DIN  256
#define DHID 256
#define DOUT 128

#define SCAN_B 256
#define SCAN_GRID ((NN + SCAN_B - 1) / SCAN_B)   // 196

// ---------------- scratch (device globals; no allocation allowed) ----------------
__device__ float g_outnorm[NN];
__device__ float g_innorm[NN];
__device__ int   g_outc[NN];
__device__ int   g_inc[NN];
__device__ int   g_rowptr[NN + 1];
__device__ int   g_cursor[NN];
__device__ int   g_poff[SCAN_B];             // block partial sums -> exclusive offsets
__device__ int   g_csrc[NE];                 // src node per CSR slot (grouped by dst)
__device__ float g_t[(size_t)NN * DHID];     // pre-aggregation transformed features

// ---------------- degree / norm / CSR kernels ----------------
__global__ void k_zero_counts() {
    int i = blockIdx.x * blockDim.x + threadIdx.x;
    if (i < NN) { g_outc[i] = 0; g_inc[i] = 0; }
}

__global__ void k_degree(const int* __restrict__ src, const int* __restrict__ dst) {
    int e = blockIdx.x * blockDim.x + threadIdx.x;
    if (e < NE) {
        atomicAdd(&g_outc[src[e]], 1);
        atomicAdd(&g_inc[dst[e]], 1);
    }
}

__global__ void k_fin_norms() {
    int i = blockIdx.x * blockDim.x + threadIdx.x;
    if (i < NN) {
        g_outnorm[i] = rsqrtf(fmaxf((float)g_outc[i], 1.f));
        g_innorm[i]  = rsqrtf(fmaxf((float)g_inc[i], 1.f));
    }
}

// ---- 3-phase multi-block exclusive scan of g_inc -> g_rowptr / g_cursor ----
// phase 1: per-block sums
__global__ void k_scan_p1() {
    __shared__ int ws[8];
    int i = blockIdx.x * SCAN_B + threadIdx.x;
    int lane = threadIdx.x & 31, wid = threadIdx.x >> 5;
    int v = (i < NN) ? g_inc[i] : 0;
#pragma unroll
    for (int o = 16; o > 0; o >>= 1) v += __shfl_down_sync(0xffffffffu, v, o);
    if (lane == 0) ws[wid] = v;
    __syncthreads();
    if (wid == 0) {
        int s = (lane < 8) ? ws[lane] : 0;
#pragma unroll
        for (int o = 4; o > 0; o >>= 1) s += __shfl_down_sync(0xffffffffu, s, o);
        if (lane == 0) g_poff[blockIdx.x] = s;
    }
}

// phase 2: single-block exclusive scan of SCAN_GRID partials
__global__ void k_scan_p2() {
    __shared__ int ws[8];
    int tid = threadIdx.x, lane = tid & 31, wid = tid >> 5;
    int v = (tid < SCAN_GRID) ? g_poff[tid] : 0;
    int x = v;
#pragma unroll
    for (int o = 1; o < 32; o <<= 1) {
        int y = __shfl_up_sync(0xffffffffu, x, o);
        if (lane >= o) x += y;
    }
    if (lane == 31) ws[wid] = x;
    __syncthreads();
    if (wid == 0 && lane < 8) {
        int s = ws[lane];
        int xs = s;
#pragma unroll
        for (int o = 1; o < 8; o <<= 1) {
            int y = __shfl_up_sync(0xffu, xs, o);
            if (lane >= o) xs += y;
        }
        ws[lane] = xs - s;   // exclusive warp offsets
    }
    __syncthreads();
    g_poff[tid] = ws[wid] + x - v;   // exclusive offset for block tid
}

// phase 3: per-block exclusive scan + global offset
__global__ void k_scan_p3() {
    __shared__ int ws[8];
    int i = blockIdx.x * SCAN_B + threadIdx.x;
    int lane = threadIdx.x & 31, wid = threadIdx.x >> 5;
    int v = (i < NN) ? g_inc[i] : 0;
    int x = v;
#pragma unroll
    for (int o = 1; o < 32; o <<= 1) {
        int y = __shfl_up_sync(0xffffffffu, x, o);
        if (lane >= o) x += y;
    }
    if (lane == 31) ws[wid] = x;
    __syncthreads();
    if (wid == 0 && lane < 8) {
        int s = ws[lane];
        int xs = s;
#pragma unroll
        for (int o = 1; o < 8; o <<= 1) {
            int y = __shfl_up_sync(0xffu, xs, o);
            if (lane >= o) xs += y;
        }
        ws[lane] = xs - s;
    }
    __syncthreads();
    if (i < NN) {
        int excl = g_poff[blockIdx.x] + ws[wid] + x - v;
        g_rowptr[i] = excl;
        g_cursor[i] = excl;
    }
    if (blockIdx.x == 0 && threadIdx.x == 0) g_rowptr[NN] = NE;
}

__global__ void k_csr_fill(const int* __restrict__ src, const int* __restrict__ dst) {
    int e = blockIdx.x * blockDim.x + threadIdx.x;
    if (e < NE) {
        int pos = atomicAdd(&g_cursor[dst[e]], 1);
        g_csrc[pos] = src[e];
    }
}

// ---------------- gather SpMM + fused epilogues ----------------
__device__ __forceinline__ void acc_add(float4& a, const float4 b) {
    a.x += b.x; a.y += b.y; a.z += b.z; a.w += b.w;
}

// h = relu(in_norm * sum_{src in N(dst)} t[src] + b1)
__global__ void k_gather_h(const float* __restrict__ t, const float* __restrict__ b1,
                           float* __restrict__ h) {
    int node = (blockIdx.x * blockDim.x + threadIdx.x) >> 5;
    int lane = threadIdx.x & 31;
    if (node >= NN) return;
    int beg = g_rowptr[node], end = g_rowptr[node + 1];
    float4 a0 = make_float4(0.f, 0.f, 0.f, 0.f);
    float4 a1 = make_float4(0.f, 0.f, 0.f, 0.f);
    int j = beg;
    for (; j + 1 < end; j += 2) {
        int s0 = g_csrc[j], s1 = g_csrc[j + 1];
        const float4* r0 = (const float4*)(t + (size_t)s0 * DHID);
        const float4* r1 = (const float4*)(t + (size_t)s1 * DHID);
        float4 v00 = r0[lane], v01 = r0[lane + 32];
        float4 v10 = r1[lane], v11 = r1[lane + 32];
        acc_add(a0, v00); acc_add(a1, v01);
        acc_add(a0, v10); acc_add(a1, v11);
    }
    if (j < end) {
        const float4* r = (const float4*)(t + (size_t)g_csrc[j] * DHID);
        acc_add(a0, r[lane]); acc_add(a1, r[lane + 32]);
    }
    float s = g_innorm[node];
    float4 bb0 = ((const float4*)b1)[lane];
    float4 bb1 = ((const float4*)b1)[lane + 32];
    float4 o0, o1;
    o0.x = fmaxf(fmaf(a0.x, s, bb0.x), 0.f); o0.y = fmaxf(fmaf(a0.y, s, bb0.y), 0.f);
    o0.z = fmaxf(fmaf(a0.z, s, bb0.z), 0.f); o0.w = fmaxf(fmaf(a0.w, s, bb0.w), 0.f);
    o1.x = fmaxf(fmaf(a1.x, s, bb1.x), 0.f); o1.y = fmaxf(fmaf(a1.y, s, bb1.y), 0.f);
    o1.z = fmaxf(fmaf(a1.z, s, bb1.z), 0.f); o1.w = fmaxf(fmaf(a1.w, s, bb1.w), 0.f);
    float4* hp = (float4*)(h + (size_t)node * DHID);
    hp[lane] = o0;
    hp[lane + 32] = o1;
}

// z = relu(agg[:, :128]*in + b2) + noise * exp(agg[:, 128:]*in + b3)
__global__ void k_gather_z(const float* __restrict__ t, const float* __restrict__ b2,
                           const float* __restrict__ b3, const float* __restrict__ noise,
                           float* __restrict__ z) {
    int node = (blockIdx.x * blockDim.x + threadIdx.x) >> 5;
    int lane = threadIdx.x & 31;
    if (node >= NN) return;
    int beg = g_rowptr[node], end = g_rowptr[node + 1];
    float4 a0 = make_float4(0.f, 0.f, 0.f, 0.f);   // mean cols
    float4 a1 = make_float4(0.f, 0.f, 0.f, 0.f);   // logstd cols
    int j = beg;
    for (; j + 1 < end; j += 2) {
        int s0 = g_csrc[j], s1 = g_csrc[j + 1];
        const float4* r0 = (const float4*)(t + (size_t)s0 * DHID);
        const float4* r1 = (const float4*)(t + (size_t)s1 * DHID);
        float4 v00 = r0[lane], v01 = r0[lane + 32];
        float4 v10 = r1[lane], v11 = r1[lane + 32];
        acc_add(a0, v00); acc_add(a1, v01);
        acc_add(a0, v10); acc_add(a1, v11);
    }
    if (j < end) {
        const float4* r = (const float4*)(t + (size_t)g_csrc[j] * DHID);
        acc_add(a0, r[lane]); acc_add(a1, r[lane + 32]);
    }
    float s = g_innorm[node];
    float4 bm = ((const float4*)b2)[lane];
    float4 bl = ((const float4*)b3)[lane];
    float4 nv = ((const float4*)(noise + (size_t)node * DOUT))[lane];
    float4 r;
    r.x = fmaxf(fmaf(a0.x, s, bm.x), 0.f) + nv.x * expf(fmaf(a1.x, s, bl.x));
    r.y = fmaxf(fmaf(a0.y, s, bm.y), 0.f) + nv.y * expf(fmaf(a1.y, s, bl.y));
    r.z = fmaxf(fmaf(a0.z, s, bm.z), 0.f) + nv.z * expf(fmaf(a1.z, s, bl.z));
    r.w = fmaxf(fmaf(a0.w, s, bm.w), 0.f) + nv.w * expf(fmaf(a1.w, s, bl.w));
    ((float4*)(z + (size_t)node * DOUT))[lane] = r;
}

// ---------------- tf32 / cp.async helpers ----------------
__device__ __forceinline__ uint32_t f2tf32(float x) {
    uint32_t r;
    asm("cvt.rna.tf32.f32 %0, %1;" : "=r"(r) : "f"(x));
    return r;
}

__device__ __forceinline__ void mma_tf32(float* c, const uint32_t* a, const uint32_t* b) {
    asm volatile(
        "mma.sync.aligned.m16n8k8.row.col.f32.tf32.tf32.f32 "
        "{%0,%1,%2,%3}, {%4,%5,%6,%7}, {%8,%9}, {%0,%1,%2,%3};"
        : "+f"(c[0]), "+f"(c[1]), "+f"(c[2]), "+f"(c[3])
        : "r"(a[0]), "r"(a[1]), "r"(a[2]), "r"(a[3]), "r"(b[0]), "r"(b[1]));
}

__device__ __forceinline__ void cp16(uint32_t dst, const void* src) {
    asm volatile("cp.async.cg.shared.global [%0], [%1], 16;" :: "r"(dst), "l"(src));
}
__device__ __forceinline__ void cp_commit() { asm volatile("cp.async.commit_group;"); }
template<int N>
__device__ __forceinline__ void cp_wait() { asm volatile("cp.async.wait_group %0;" :: "n"(N)); }

// ---------------- tensor-core GEMM (cp.async double-buffered) ----------------
// C[M,Ncols] = (A @ B) * rowscale (applied to output rows; == (A*rowscale) @ B)
// TRANSB=0: B(k,n)=B[k*ld+n]; SPLITB: cols [0,128)->B0, [128,256)->B1 (ld=DOUT)
// TRANSB=1: B(k,n)=B0[n*K+k]
template<int TRANSB, int SPLITB>
__global__ void __launch_bounds__(256, 2)
k_gemm_mma(const float* __restrict__ A, const float* __restrict__ rowscale,
           const float* __restrict__ B0, const float* __restrict__ B1,
           float* __restrict__ C, int M, int Ncols, int K)
{
    constexpr int BM = 128, BN = 128, BK = 16;
    constexpr int ALD = BK + 4;                      // 20 floats/row, 16B-aligned stride
    constexpr int BSZ = TRANSB ? (BN * ALD) : (BK * (BN + 8));
    __shared__ float As[2][BM * ALD];
    __shared__ float Bs[2][BSZ];

    const int tid  = threadIdx.x;
    const int lane = tid & 31;
    const int warp = tid >> 5;
    const int row0 = blockIdx.y * BM;
    const int col0 = blockIdx.x * BN;
    const int warpM = (warp >> 2) * 64;
    const int warpN = (warp & 3) * 32;

    float acc[4][4][4];
#pragma unroll
    for (int i = 0; i < 4; i++)
#pragma unroll
        for (int j = 0; j < 4; j++)
#pragma unroll
            for (int r = 0; r < 4; r++) acc[i][j][r] = 0.f;

    const int ar = tid >> 2;          // row 0..63 (+64 on 2nd pass)
    const int ak4 = tid & 3;          // k quad
    const int bkr = tid >> 5;         // k row 0..7 (+8)
    const int bn4 = tid & 31;         // n quad

    const float* bbase;
    int bld = 0;
    if constexpr (TRANSB) {
        bbase = B0;                   // [Ncols][K]
    } else if constexpr (SPLITB) {
        bbase = (col0 == 0) ? B0 : B1;
        bld = DOUT;
    } else {
        bbase = B0 + col0;
        bld = Ncols;
    }

    auto stage = [&](int k0, int buf) {
#pragma unroll
        for (int i = 0; i < 2; i++) {
            int r = ar + i * 64;
            int gr = row0 + r;
            if (gr >= M) gr = M - 1;                  // clamp; OOB rows never stored
            cp16((uint32_t)__cvta_generic_to_shared(&As[buf][r * ALD + ak4 * 4]),
                 A + (size_t)gr * K + k0 + ak4 * 4);
        }
        if constexpr (TRANSB) {
#pragma unroll
            for (int i = 0; i < 2; i++) {
                int r = ar + i * 64;                  // n index
                cp16((uint32_t)__cvta_generic_to_shared(&Bs[buf][r * ALD + ak4 * 4]),
                     bbase + (size_t)(col0 + r) * K + k0 + ak4 * 4);
            }
        } else {
#pragma unroll
            for (int i = 0; i < 2; i++) {
                int k = bkr + i * 8;
                cp16((uint32_t)__cvta_generic_to_shared(&Bs[buf][k * (BN + 8) + bn4 * 4]),
                     bbase + (size_t)(k0 + k) * bld + bn4 * 4);
            }
        }
    };

    const int NT = K / BK;
    stage(0, 0);
    cp_commit();

    for (int t = 0; t < NT; t++) {
        int buf = t & 1;
        if (t + 1 < NT) {
            stage((t + 1) * BK, buf ^ 1);
            cp_commit();
            cp_wait<1>();
        } else {
            cp_wait<0>();
        }
        __syncthreads();

#pragma unroll
        for (int ks = 0; ks < 2; ks++) {
            uint32_t a[4][4], b[4][2];
#pragma unroll
            for (int mi = 0; mi < 4; mi++) {
                const float* ap = &As[buf][(warpM + mi * 16 + (lane >> 2)) * ALD + ks * 8 + (lane & 3)];
                a[mi][0] = f2tf32(ap[0]);
                a[mi][1] = f2tf32(ap[8 * ALD]);
                a[mi][2] = f2tf32(ap[4]);
                a[mi][3] = f2tf32(ap[8 * ALD + 4]);
            }
#pragma unroll
            for (int ni = 0; ni < 4; ni++) {
                if constexpr (TRANSB) {
                    const float* bp = &Bs[buf][(warpN + ni * 8 + (lane >> 2)) * ALD + ks * 8 + (lane & 3)];
                    b[ni][0] = f2tf32(bp[0]);
                    b[ni][1] = f2tf32(bp[4]);
                } else {
                    const float* bp = &Bs[buf][(ks * 8 + (lane & 3)) * (BN + 8) + warpN + ni * 8 + (lane >> 2)];
                    b[ni][0] = f2tf32(bp[0]);
                    b[ni][1] = f2tf32(bp[4 * (BN + 8)]);
                }
            }
#pragma unroll
            for (int mi = 0; mi < 4; mi++)
#pragma unroll
                for (int ni = 0; ni < 4; ni++)
                    mma_tf32(acc[mi][ni], a[mi], b[ni]);
        }
        __syncthreads();
    }

    // epilogue: apply rowscale to output rows, store fp32
#pragma unroll
    for (int mi = 0; mi < 4; mi++) {
        int gr0 = row0 + warpM + mi * 16 + (lane >> 2);
        float s0 = 1.f, s1 = 1.f;
        if (rowscale) {
            if (gr0 < M)     s0 = rowscale[gr0];
            if (gr0 + 8 < M) s1 = rowscale[gr0 + 8];
        }
#pragma unroll
        for (int ni = 0; ni < 4; ni++) {
            int col = col0 + warpN + ni * 8 + (lane & 3) * 2;
            if (gr0 < M)
                *(float2*)(C + (size_t)gr0 * Ncols + col) =
                    make_float2(acc[mi][ni][0] * s0, acc[mi][ni][1] * s0);
            if (gr0 + 8 < M)
                *(float2*)(C + (size_t)(gr0 + 8) * Ncols + col) =
                    make_float2(acc[mi][ni][2] * s1, acc[mi][ni][3] * s1);
        }
    }
}

// ---------------- launch ----------------
extern "C" void kernel_launch(void* const* d_in, const int* in_sizes, int n_in,
                              void* d_out, int out_size)
{
    const float* features = (const float*)d_in[0];
    const float* noise    = (const float*)d_in[1];
    const float* W1       = (const float*)d_in[2];
    const float* b1       = (const float*)d_in[3];
    const float* W2       = (const float*)d_in[4];
    const float* b2       = (const float*)d_in[5];
    const float* W3       = (const float*)d_in[6];
    const float* b3       = (const float*)d_in[7];
    const float* fcW      = (const float*)d_in[8];
    const int*   src      = (const int*)d_in[9];
    const int*   dst      = (const int*)d_in[10];

    float* out     = (float*)d_out;
    float* z_out   = out;                                 // [NN, 128]
    float* h_out   = out + (size_t)NN * DOUT;             // [NN, 256]
    float* seq_out = h_out + (size_t)NN * DHID;           // [NN, 256]

    float *pt, *pon;
    cudaGetSymbolAddress((void**)&pt,  g_t);
    cudaGetSymbolAddress((void**)&pon, g_outnorm);

    const int T = 256;
    // degrees, norms, CSR by dst
    k_zero_counts<<<(NN + T - 1) / T, T>>>();
    k_degree<<<(NE + T - 1) / T, T>>>(src, dst);
    k_fin_norms<<<(NN + T - 1) / T, T>>>();
    k_scan_p1<<<SCAN_GRID, SCAN_B>>>();
    k_scan_p2<<<1, SCAN_B>>>();
    k_scan_p3<<<SCAN_GRID, SCAN_B>>>();
    k_csr_fill<<<(NE + T - 1) / T, T>>>(src, dst);

    dim3 ggrid(2, (NN + 127) / 128);
    const int gather_blocks = (NN * 32 + T - 1) / T;

    // layer 1
    k_gemm_mma<0, 0><<<ggrid, T>>>(features, pon, W1, nullptr, pt, NN, DHID, DIN);
    k_gather_h<<<gather_blocks, T>>>(pt, b1, h_out);

    // layer 2 (W2|W3 fused)
    k_gemm_mma<0, 1><<<ggrid, T>>>(h_out, pon, W2, W3, pt, NN, DHID, DHID);
    k_gather_z<<<gather_blocks, T>>>(pt, b2, b3, noise, z_out);

    // seq_fts = features @ fcW^T
    k_gemm_mma<1, 0><<<ggrid, T>>>(features, nullptr, fcW, nullptr, seq_out, NN, DIN, DIN);
}